// round 13
// baseline (speedup 1.0000x reference)
#include <cuda_runtime.h>
#include <cuda_bf16.h>
#include <cstdint>

#define NMAX 1000000
#define CC 16
#define KS 9
#define TPB 128                 // 4 warps
#define WPC 4
#define GRID_CONV 444           // 148 SMs * 3 CTAs
#define BUF 9216                // one staging buffer: 18 chunks * 512B
#define WSTRIDE (2 * BUF)       // double-buffered per warp
#define SMEM_BYTES (WPC * WSTRIDE)   // 73728

typedef unsigned int uint;

// ---------------- device scratch ----------------
__device__ float g_z1[(size_t)NMAX * CC];
__device__ float g_z2[(size_t)NMAX * CC];
__device__ uint4 g_dhl[(size_t)NMAX * 4];   // row 64B: [hi c0-7 |hi c8-15 |lo c0-7 |lo c8-15]
__device__ uint4 g_ahl[(size_t)NMAX * 4];
__device__ float g_stats[64];               // sum1, sumsq1, sum2, sumsq2

// ---------------- helpers ----------------
__device__ __forceinline__ uint32_t smem_u32(const void* p) {
    uint32_t a;
    asm("{ .reg .u64 t; cvta.to.shared.u64 t, %1; cvt.u32.u64 %0, t; }" : "=r"(a) : "l"(p));
    return a;
}
__device__ __forceinline__ void ldsm4(uint32_t* a, uint32_t addr) {
    asm volatile("ldmatrix.sync.aligned.m8n8.x4.shared.b16 {%0,%1,%2,%3}, [%4];"
                 : "=r"(a[0]), "=r"(a[1]), "=r"(a[2]), "=r"(a[3]) : "r"(addr));
}
__device__ __forceinline__ void mma16816(float* c, const uint32_t* a, uint32_t b0, uint32_t b1) {
    asm volatile("mma.sync.aligned.m16n8k16.row.col.f32.bf16.bf16.f32 "
                 "{%0,%1,%2,%3}, {%4,%5,%6,%7}, {%8,%9}, {%0,%1,%2,%3};"
                 : "+f"(c[0]), "+f"(c[1]), "+f"(c[2]), "+f"(c[3])
                 : "r"(a[0]), "r"(a[1]), "r"(a[2]), "r"(a[3]), "r"(b0), "r"(b1));
}
__device__ __forceinline__ float leaky(float x) { return fmaxf(x, 0.2f * x); }

__device__ __forceinline__ uint bits2(__nv_bfloat162 v) {
    return *reinterpret_cast<uint*>(&v);
}
__device__ __forceinline__ uint packhl(float x, float y, uint& lo_out) {
    __nv_bfloat16 hx = __float2bfloat16_rn(x);
    __nv_bfloat16 hy = __float2bfloat16_rn(y);
    __nv_bfloat16 lx = __float2bfloat16_rn(x - __bfloat162float(hx));
    __nv_bfloat16 ly = __float2bfloat16_rn(y - __bfloat162float(hy));
    lo_out = (uint)__bfloat16_as_ushort(lx) | ((uint)__bfloat16_as_ushort(ly) << 16);
    return (uint)__bfloat16_as_ushort(hx) | ((uint)__bfloat16_as_ushort(hy) << 16);
}
// split 8 floats -> 16B hi + 16B lo
__device__ __forceinline__ void split8(const float* v, uint4& hi, uint4& lo) {
    uint l0, l1, l2, l3;
    hi.x = packhl(v[0], v[1], l0);
    hi.y = packhl(v[2], v[3], l1);
    hi.z = packhl(v[4], v[5], l2);
    hi.w = packhl(v[6], v[7], l3);
    lo = make_uint4(l0, l1, l2, l3);
}

// ---------------------------------------------------------------------------
// k0: zero stats + split data -> g_dhl
// ---------------------------------------------------------------------------
__global__ __launch_bounds__(256) void k0_split(const float* __restrict__ data, int N) {
    int g = blockIdx.x * 256 + threadIdx.x;
    if (g < 64) g_stats[g] = 0.0f;
    if (g >= 2 * N) return;
    int p = g >> 1, h = g & 1;          // h: which 8-channel half
    const float4* s = reinterpret_cast<const float4*>(data) + (size_t)p * 4 + h * 2;
    float4 a = s[0], b = s[1];
    float v[8] = {a.x, a.y, a.z, a.w, b.x, b.y, b.z, b.w};
    uint4 hi, lo;
    split8(v, hi, lo);
    g_dhl[(size_t)p * 4 + h] = hi;
    g_dhl[(size_t)p * 4 + 2 + h] = lo;
}

// ---------------------------------------------------------------------------
// gather helpers
// ---------------------------------------------------------------------------
__device__ __forceinline__ void load_iv(const int* __restrict__ ind, int t,
                                        unsigned indmax, int lane, int* iv) {
#pragma unroll
    for (int i = 0; i < 5; ++i) {
        unsigned u = (unsigned)(i * 32 + lane);
        unsigned off = (unsigned)t * 144u + (u < 144u ? u : 0u);
        iv[i] = __ldg(ind + (off <= indmax ? off : indmax));
    }
}

__device__ __forceinline__ void issue_gather(const uint4* __restrict__ src,
                                             const int* iv, int grp, int q,
                                             uint32_t bufbase) {
    const uint32_t segoff = ((uint32_t)(q & 1)) << 4;
    const uint32_t cjadd = (q >> 1) ? 9u : 0u;
#pragma unroll
    for (int i = 0; i < 18; ++i) {
        int u = i * 8 + grp;
        int idxv = __shfl_sync(0xffffffffu, iv[i >> 2], u & 31);
        int pt = (u * 57) >> 9;          // u/9 for u<512
        int j = u - pt * 9;
        uint32_t x = (((uint32_t)pt >> 2) & 1u) << 4;
        uint32_t dst = bufbase + ((uint32_t)j + cjadd) * 512u + (uint32_t)pt * 32u +
                       (segoff ^ x);
        const char* gsrc = reinterpret_cast<const char*>(src) +
                           (size_t)(unsigned)idxv * 64u + (unsigned)q * 16u;
        asm volatile("cp.async.cg.shared.global [%0], [%1], 16;"
                     :: "r"(dst), "l"(gsrc) : "memory");
    }
    asm volatile("cp.async.commit_group;" ::: "memory");
}

// ---------------------------------------------------------------------------
// conv via mma.sync + cp.async double-buffered gather of pre-split rows.
// FIRST: src=g_dhl, +bias, out g_z1, stats[0:32)
// else : src=g_ahl (BN1+leaky already applied by k1b), out g_z2, stats[32:64)
// ---------------------------------------------------------------------------
template <bool FIRST>
__global__ __launch_bounds__(TPB, 3) void conv_mma(
    const int* __restrict__ ind, const float* __restrict__ w,
    const float* __restrict__ bias, int N, int ntiles)
{
    extern __shared__ __align__(16) char smraw[];
    const int tid = threadIdx.x, wid = tid >> 5, lane = tid & 31;
    const uint32_t buf0 = smem_u32(smraw) + (uint32_t)wid * WSTRIDE;

    const uint4* __restrict__ src = FIRST ? g_dhl : g_ahl;
    float* __restrict__ zout = FIRST ? g_z1 : g_z2;

    const int t4 = lane & 3;
    const int nrow = lane >> 2;
    const int q = lane & 3;
    const int grp = lane >> 2;

    // ---- B fragments in registers (hi & lo) — tile-invariant ----
    uint32_t bh[KS][2][2], bl[KS][2][2];
#pragma unroll
    for (int j = 0; j < KS; ++j) {
#pragma unroll
        for (int nf = 0; nf < 2; ++nf) {
            int n = nf * 8 + nrow;
            int k0 = t4 * 2;
            float w00 = __ldg(w + ((k0 + 0) * CC + n) * KS + j);
            float w01 = __ldg(w + ((k0 + 1) * CC + n) * KS + j);
            float w10 = __ldg(w + ((k0 + 8) * CC + n) * KS + j);
            float w11 = __ldg(w + ((k0 + 9) * CC + n) * KS + j);
            uint lo;
            bh[j][nf][0] = packhl(w00, w01, lo); bl[j][nf][0] = lo;
            bh[j][nf][1] = packhl(w10, w11, lo); bl[j][nf][1] = lo;
        }
    }

    float bia[4] = {0, 0, 0, 0};
    if (FIRST) {
        bia[0] = __ldg(bias + 2 * t4);
        bia[1] = __ldg(bias + 2 * t4 + 1);
        bia[2] = __ldg(bias + 2 * t4 + 8);
        bia[3] = __ldg(bias + 2 * t4 + 9);
    }

    // ldmatrix per-lane offset (R5-verified xor-seg layout, 512B chunks)
    const uint32_t lr = lane & 15;
    const uint32_t lseg = (uint32_t)(lane >> 4) ^ ((lr >> 2) & 1);
    const uint32_t lmoff = lr * 32 + lseg * 16;

    float s[4] = {0, 0, 0, 0}, qq[4] = {0, 0, 0, 0};
    const unsigned indmax = (unsigned)N * KS - 1u;
    const int wstep = GRID_CONV * WPC;

    int t = blockIdx.x * WPC + wid;
    if (t < ntiles) {
        int ivc[5], ivN[5];
        load_iv(ind, t, indmax, lane, ivc);
        issue_gather(src, ivc, grp, q, buf0);            // tile t -> buf 0
        load_iv(ind, t + wstep, indmax, lane, ivN);      // indices for t+1
        int sel = 0;

        for (; t < ntiles; t += wstep) {
            // 1. issue next tile's gather into the other buffer (clamped-safe)
            issue_gather(src, ivN, grp, q, buf0 + (uint32_t)(sel ^ 1) * BUF);
            // 2. prefetch indices two tiles ahead
            int ivNN[5];
            load_iv(ind, t + 2 * wstep, indmax, lane, ivNN);
            // 3. wait for current tile's data
            asm volatile("cp.async.wait_group 1;" ::: "memory");
            __syncwarp();

            // 4. MMA: 9 chunks x (Ahi*Bhi + Ahi*Blo + Alo*Bhi) x 2 n-frags
            const uint32_t bb = buf0 + (uint32_t)sel * BUF;
            float c0[4] = {0, 0, 0, 0}, c1[4] = {0, 0, 0, 0};
#pragma unroll
            for (int j = 0; j < KS; ++j) {
                uint32_t ah[4], al[4];
                ldsm4(ah, bb + (uint32_t)j * 512u + lmoff);
                ldsm4(al, bb + (uint32_t)(9 + j) * 512u + lmoff);
                mma16816(c0, ah, bh[j][0][0], bh[j][0][1]);
                mma16816(c1, ah, bh[j][1][0], bh[j][1][1]);
                mma16816(c0, ah, bl[j][0][0], bl[j][0][1]);
                mma16816(c1, ah, bl[j][1][0], bl[j][1][1]);
                mma16816(c0, al, bh[j][0][0], bh[j][0][1]);
                mma16816(c1, al, bh[j][1][0], bh[j][1][1]);
            }

            // 5. epilogue: bias, z store, stats
            int base = t * 16;
            int pA = base + nrow;
            int pB = pA + 8;
            float zA0 = c0[0] + bia[0], zA1 = c0[1] + bia[1];
            float zA2 = c1[0] + bia[2], zA3 = c1[1] + bia[3];
            float zB0 = c0[2] + bia[0], zB1 = c0[3] + bia[1];
            float zB2 = c1[2] + bia[2], zB3 = c1[3] + bia[3];

            if (pA < N) {
                float* zr = zout + (size_t)pA * CC + 2 * t4;
                reinterpret_cast<float2*>(zr)[0] = make_float2(zA0, zA1);
                reinterpret_cast<float2*>(zr + 8)[0] = make_float2(zA2, zA3);
                s[0] += zA0; s[1] += zA1; s[2] += zA2; s[3] += zA3;
                qq[0] += zA0 * zA0; qq[1] += zA1 * zA1;
                qq[2] += zA2 * zA2; qq[3] += zA3 * zA3;
            }
            if (pB < N) {
                float* zr = zout + (size_t)pB * CC + 2 * t4;
                reinterpret_cast<float2*>(zr)[0] = make_float2(zB0, zB1);
                reinterpret_cast<float2*>(zr + 8)[0] = make_float2(zB2, zB3);
                s[0] += zB0; s[1] += zB1; s[2] += zB2; s[3] += zB3;
                qq[0] += zB0 * zB0; qq[1] += zB1 * zB1;
                qq[2] += zB2 * zB2; qq[3] += zB3 * zB3;
            }

#pragma unroll
            for (int i = 0; i < 5; ++i) ivc[i] = ivN[i];
#pragma unroll
            for (int i = 0; i < 5; ++i) ivN[i] = ivNN[i];
            sel ^= 1;
        }
        asm volatile("cp.async.wait_group 0;" ::: "memory");
    }

    // ---- stats: butterfly over lanes sharing t4, then 4 atomics/lane ----
#pragma unroll
    for (int off = 4; off <= 16; off <<= 1) {
#pragma unroll
        for (int k = 0; k < 4; ++k) {
            s[k] += __shfl_xor_sync(0xffffffffu, s[k], off);
            qq[k] += __shfl_xor_sync(0xffffffffu, qq[k], off);
        }
    }
    if (lane < 4) {
        const int soff = FIRST ? 0 : 32;
        int ch[4] = {2 * lane, 2 * lane + 1, 2 * lane + 8, 2 * lane + 9};
#pragma unroll
        for (int k = 0; k < 4; ++k) {
            atomicAdd(&g_stats[soff + ch[k]], s[k]);
            atomicAdd(&g_stats[soff + 16 + ch[k]], qq[k]);
        }
    }
}

// ---------------------------------------------------------------------------
// k1b: act = leaky(bn1(z1)); split -> g_ahl
// ---------------------------------------------------------------------------
__global__ __launch_bounds__(256) void k1b_actsplit(
    const float* __restrict__ gamma1, const float* __restrict__ beta1, int N, float invN)
{
    __shared__ float as_[CC], cs_[CC];
    if (threadIdx.x < CC) {
        int o = threadIdx.x;
        float mean = g_stats[o] * invN;
        float var = g_stats[16 + o] * invN - mean * mean;
        float a = gamma1[o] * rsqrtf(var + 1e-5f);
        as_[o] = a;
        cs_[o] = fmaf(-mean, a, beta1[o]);
    }
    __syncthreads();
    int g = blockIdx.x * 256 + threadIdx.x;
    if (g >= 2 * N) return;
    int p = g >> 1, h = g & 1;
    const float4* sp = reinterpret_cast<const float4*>(g_z1) + (size_t)p * 4 + h * 2;
    float4 a = sp[0], b = sp[1];
    float v[8] = {a.x, a.y, a.z, a.w, b.x, b.y, b.z, b.w};
#pragma unroll
    for (int k = 0; k < 8; ++k) {
        int c = h * 8 + k;
        v[k] = leaky(fmaf(as_[c], v[k], cs_[c]));
    }
    uint4 hi, lo;
    split8(v, hi, lo);
    g_ahl[(size_t)p * 4 + h] = hi;
    g_ahl[(size_t)p * 4 + 2 + h] = lo;
}

// ---------------------------------------------------------------------------
// k3: out = leaky(bn2(z2) + data)
// ---------------------------------------------------------------------------
__global__ __launch_bounds__(256) void k3_epilogue(
    const float* __restrict__ data, const float* __restrict__ gamma2,
    const float* __restrict__ beta2, float* __restrict__ out, int N, float invN)
{
    __shared__ float a2s[CC], c2s[CC];
    if (threadIdx.x < CC) {
        int o = threadIdx.x;
        float mean = g_stats[32 + o] * invN;
        float var = g_stats[48 + o] * invN - mean * mean;
        float a = gamma2[o] * rsqrtf(var + 1e-5f);
        a2s[o] = a;
        c2s[o] = fmaf(-mean, a, beta2[o]);
    }
    __syncthreads();
    int total4 = N * 4;
    const float4* z4 = reinterpret_cast<const float4*>(g_z2);
    const float4* d4 = reinterpret_cast<const float4*>(data);
    float4* o4 = reinterpret_cast<float4*>(out);
    for (int i = blockIdx.x * blockDim.x + threadIdx.x; i < total4;
         i += gridDim.x * blockDim.x) {
        float4 zv = z4[i];
        float4 dv = d4[i];
        int cb = (i & 3) * 4;
        float4 r;
        r.x = leaky(fmaf(a2s[cb + 0], zv.x, c2s[cb + 0]) + dv.x);
        r.y = leaky(fmaf(a2s[cb + 1], zv.y, c2s[cb + 1]) + dv.y);
        r.z = leaky(fmaf(a2s[cb + 2], zv.z, c2s[cb + 2]) + dv.z);
        r.w = leaky(fmaf(a2s[cb + 3], zv.w, c2s[cb + 3]) + dv.w);
        o4[i] = r;
    }
}

extern "C" void kernel_launch(void* const* d_in, const int* in_sizes, int n_in,
                              void* d_out, int out_size)
{
    const float* data   = (const float*)d_in[0];
    const int*   ind    = (const int*)d_in[1];
    const float* w1     = (const float*)d_in[2];
    const float* b1     = (const float*)d_in[3];
    const float* gamma1 = (const float*)d_in[4];
    const float* beta1  = (const float*)d_in[5];
    const float* w2     = (const float*)d_in[6];
    const float* gamma2 = (const float*)d_in[7];
    const float* beta2  = (const float*)d_in[8];

    int N = in_sizes[0] / CC;
    if (N > NMAX) N = NMAX;
    float invN = 1.0f / (float)N;
    int ntiles = (N + 15) / 16;
    int gsplit = (2 * N + 255) / 256;

    cudaFuncSetAttribute(conv_mma<true>,
                         cudaFuncAttributeMaxDynamicSharedMemorySize, SMEM_BYTES);
    cudaFuncSetAttribute(conv_mma<false>,
                         cudaFuncAttributeMaxDynamicSharedMemorySize, SMEM_BYTES);

    k0_split<<<gsplit, 256>>>(data, N);
    conv_mma<true><<<GRID_CONV, TPB, SMEM_BYTES>>>(ind, w1, b1, N, ntiles);
    k1b_actsplit<<<gsplit, 256>>>(gamma1, beta1, N, invN);
    conv_mma<false><<<GRID_CONV, TPB, SMEM_BYTES>>>(ind, w2, nullptr, N, ntiles);
    k3_epilogue<<<1024, 256>>>(data, gamma2, beta2, (float*)d_out, N, invN);
}

// round 15
// speedup vs baseline: 2.0648x; 2.0648x over previous
#include <cuda_runtime.h>
#include <cuda_bf16.h>
#include <cstdint>

#define NMAX 1000000
#define CC 16
#define KS 9
#define NKC 18                  // k-chunks of 8 (K = 144)
#define TPB 128                 // 4 warps
#define WPC 4
#define GRID_CONV 444           // 148 SMs * 3 CTAs
#define COEF 128
#define WSTRIDE (NKC * 512)     // 9216 per warp
#define SMEM_BYTES (COEF + WPC * WSTRIDE)   // 36992 < 48K

typedef unsigned int uint;

// ---------------- device scratch ----------------
__device__ float g_z1[(size_t)NMAX * CC];
__device__ float g_z2[(size_t)NMAX * CC];
__device__ float g_stats[64];   // sum1, sumsq1, sum2, sumsq2

// ---------------- helpers ----------------
__device__ __forceinline__ uint32_t smem_u32(const void* p) {
    uint32_t a;
    asm("{ .reg .u64 t; cvta.to.shared.u64 t, %1; cvt.u32.u64 %0, t; }" : "=r"(a) : "l"(p));
    return a;
}
__device__ __forceinline__ void ldsm4(uint32_t* a, uint32_t addr) {
    asm volatile("ldmatrix.sync.aligned.m8n8.x4.shared.b16 {%0,%1,%2,%3}, [%4];"
                 : "=r"(a[0]), "=r"(a[1]), "=r"(a[2]), "=r"(a[3]) : "r"(addr));
}
__device__ __forceinline__ void mmatf32(float* c, const uint32_t* a, uint32_t b0, uint32_t b1) {
    asm volatile("mma.sync.aligned.m16n8k8.row.col.f32.tf32.tf32.f32 "
                 "{%0,%1,%2,%3}, {%4,%5,%6,%7}, {%8,%9}, {%0,%1,%2,%3};"
                 : "+f"(c[0]), "+f"(c[1]), "+f"(c[2]), "+f"(c[3])
                 : "r"(a[0]), "r"(a[1]), "r"(a[2]), "r"(a[3]), "r"(b0), "r"(b1));
}
__device__ __forceinline__ uint cvt_tf32(float x) {
    uint r;
    asm("cvt.rna.tf32.f32 %0, %1;" : "=r"(r) : "f"(x));
    return r;
}
__device__ __forceinline__ float leaky(float x) { return fmaxf(x, 0.2f * x); }

// ---------------------------------------------------------------------------
// k0: zero the stats accumulators
// ---------------------------------------------------------------------------
__global__ void k0_zero() {
    if (threadIdx.x < 64) g_stats[threadIdx.x] = 0.0f;
}

// ---------------------------------------------------------------------------
// conv via tf32 mma.sync (single pass, no hi/lo split):
//   quad-cooperative fp32 gather -> cvt.rna.tf32 -> conflict-free STS ->
//   ldmatrix x4 per 8-wide k-chunk -> 36 MMA/tile.
// FIRST: src=data, +bias, out g_z1, stats[0:32)
// else : src=g_z1, BN1+leaky fused, out g_z2, stats[32:64)
// ---------------------------------------------------------------------------
template <bool FIRST>
__global__ __launch_bounds__(TPB, 3) void conv_mma(
    const float* __restrict__ src_ext, const int* __restrict__ ind,
    const float* __restrict__ w, const float* __restrict__ bias,
    const float* __restrict__ gamma, const float* __restrict__ beta,
    int N, int ntiles, float invN)
{
    extern __shared__ __align__(16) char smraw[];
    const int tid = threadIdx.x, wid = tid >> 5, lane = tid & 31;
    float* const coefA = reinterpret_cast<float*>(smraw);
    float* const coefC = coefA + CC;
    char* const stage = smraw + COEF + wid * WSTRIDE;
    const uint32_t stage32 = smem_u32(stage);

    const float4* __restrict__ src =
        FIRST ? reinterpret_cast<const float4*>(src_ext)
              : reinterpret_cast<const float4*>(g_z1);
    float* __restrict__ zout = FIRST ? g_z1 : g_z2;

    const int t4 = lane & 3;
    const int nrow = lane >> 2;
    const int q = lane & 3;
    const int grp = lane >> 2;

    // ---- B fragments in registers (tf32), tile-invariant ----
    // chunk kc: k = kc*8 + klocal; k = j*16 + c  =>  j = kc>>1, c = (kc&1)*8 + klocal
    uint32_t bt[NKC][2][2];
#pragma unroll
    for (int kc = 0; kc < NKC; ++kc) {
        int j = kc >> 1, co = (kc & 1) * 8;
#pragma unroll
        for (int nf = 0; nf < 2; ++nf) {
            int n = nf * 8 + nrow;
            bt[kc][nf][0] = cvt_tf32(__ldg(w + ((co + t4) * CC + n) * KS + j));
            bt[kc][nf][1] = cvt_tf32(__ldg(w + ((co + 4 + t4) * CC + n) * KS + j));
        }
    }

    if (!FIRST) {
        if (tid < CC) {
            float mean = g_stats[tid] * invN;
            float var = g_stats[16 + tid] * invN - mean * mean;
            float a = __ldg(gamma + tid) * rsqrtf(var + 1e-5f);
            coefA[tid] = a;
            coefC[tid] = fmaf(-mean, a, __ldg(beta + tid));
        }
        __syncthreads();
    }

    float a1v[4], c1v[4];
    if (!FIRST) {
#pragma unroll
        for (int k = 0; k < 4; ++k) { a1v[k] = coefA[4 * q + k]; c1v[k] = coefC[4 * q + k]; }
    }
    float bia[4] = {0, 0, 0, 0};
    if (FIRST) {
        bia[0] = __ldg(bias + 2 * t4);
        bia[1] = __ldg(bias + 2 * t4 + 1);
        bia[2] = __ldg(bias + 2 * t4 + 8);
        bia[3] = __ldg(bias + 2 * t4 + 9);
    }

    // ldmatrix lane role: matrices m0..m3 = (rows0-7,c0-3),(rows8-15,c0-3),
    // (rows0-7,c4-7),(rows8-15,c4-7). lane&15 = logical row, lane>>4 = col half.
    const uint32_t lrow = (uint32_t)(lane & 15);
    const uint32_t colsel = ((uint32_t)(lane >> 4)) << 4;

    float s[4] = {0, 0, 0, 0}, qq[4] = {0, 0, 0, 0};
    const unsigned indmax = (unsigned)N * KS - 1u;
    const int wstep = GRID_CONV * WPC;

    int t = blockIdx.x * WPC + wid;
    int iv[5];
    if (t < ntiles) {
#pragma unroll
        for (int i = 0; i < 5; ++i) {
            unsigned u = (unsigned)(i * 32 + lane);
            unsigned off = (unsigned)(t * 16) * KS + (u < 144u ? u : 0u);
            iv[i] = __ldg(ind + (off <= indmax ? off : indmax));
        }
    }

    for (; t < ntiles; t += wstep) {
        const int base = t * 16;

        // ---- gather + cvt + STS, 2 batches of 9 (MLP=9) ----
#pragma unroll
        for (int b = 0; b < 2; ++b) {
            int idx[9];
#pragma unroll
            for (int k = 0; k < 9; ++k) {
                int i = b * 9 + k;
                idx[k] = __shfl_sync(0xffffffffu, iv[i >> 2], ((i & 3) << 3) + grp);
            }
            float4 v[9];
#pragma unroll
            for (int k = 0; k < 9; ++k)
                v[k] = __ldg(src + (size_t)(unsigned)idx[k] * 4 + q);
#pragma unroll
            for (int k = 0; k < 9; ++k) {
                float4 x = v[k];
                if (!FIRST) {
                    x.x = leaky(fmaf(a1v[0], x.x, c1v[0]));
                    x.y = leaky(fmaf(a1v[1], x.y, c1v[1]));
                    x.z = leaky(fmaf(a1v[2], x.z, c1v[2]));
                    x.w = leaky(fmaf(a1v[3], x.w, c1v[3]));
                }
                uint4 tv = make_uint4(cvt_tf32(x.x), cvt_tf32(x.y),
                                      cvt_tf32(x.z), cvt_tf32(x.w));
                int u = (b * 9 + k) * 8 + grp;
                int pt = (u * 57) >> 9;        // u/9
                int j = u - pt * 9;
                uint32_t kc = (uint32_t)(j * 2) + ((uint32_t)q >> 1);
                uint32_t rs = (uint32_t)pt ^ (kc & 3u);
                uint32_t off = kc * 512u + rs * 32u +
                               ((((uint32_t)q & 1u) << 4) ^ ((rs & 4u) << 2));
                *reinterpret_cast<uint4*>(stage + off) = tv;
            }
        }

        // ---- prefetch next tile's indices ----
        int tn = t + wstep;
        int ivn[5];
        if (tn < ntiles) {
#pragma unroll
            for (int i = 0; i < 5; ++i) {
                unsigned u = (unsigned)(i * 32 + lane);
                unsigned off = (unsigned)(tn * 16) * KS + (u < 144u ? u : 0u);
                ivn[i] = __ldg(ind + (off <= indmax ? off : indmax));
            }
        }
        __syncwarp();

        // ---- MMA: 18 k-chunks x 2 n-frags ----
        float c0[4] = {0, 0, 0, 0}, c1[4] = {0, 0, 0, 0};
#pragma unroll
        for (int kc = 0; kc < NKC; ++kc) {
            uint32_t rs = lrow ^ ((uint32_t)kc & 3u);
            uint32_t addr = stage32 + (uint32_t)kc * 512u + rs * 32u +
                            (colsel ^ ((rs & 4u) << 2));
            uint32_t a[4];
            ldsm4(a, addr);
            mmatf32(c0, a, bt[kc][0][0], bt[kc][0][1]);
            mmatf32(c1, a, bt[kc][1][0], bt[kc][1][1]);
        }

        // ---- epilogue: bias, z store, stats ----
        int pA = base + nrow;
        int pB = pA + 8;
        float zA0 = c0[0] + bia[0], zA1 = c0[1] + bia[1];
        float zA2 = c1[0] + bia[2], zA3 = c1[1] + bia[3];
        float zB0 = c0[2] + bia[0], zB1 = c0[3] + bia[1];
        float zB2 = c1[2] + bia[2], zB3 = c1[3] + bia[3];

        if (pA < N) {
            float* zr = zout + (size_t)pA * CC + 2 * t4;
            reinterpret_cast<float2*>(zr)[0] = make_float2(zA0, zA1);
            reinterpret_cast<float2*>(zr + 8)[0] = make_float2(zA2, zA3);
            s[0] += zA0; s[1] += zA1; s[2] += zA2; s[3] += zA3;
            qq[0] += zA0 * zA0; qq[1] += zA1 * zA1;
            qq[2] += zA2 * zA2; qq[3] += zA3 * zA3;
        }
        if (pB < N) {
            float* zr = zout + (size_t)pB * CC + 2 * t4;
            reinterpret_cast<float2*>(zr)[0] = make_float2(zB0, zB1);
            reinterpret_cast<float2*>(zr + 8)[0] = make_float2(zB2, zB3);
            s[0] += zB0; s[1] += zB1; s[2] += zB2; s[3] += zB3;
            qq[0] += zB0 * zB0; qq[1] += zB1 * zB1;
            qq[2] += zB2 * zB2; qq[3] += zB3 * zB3;
        }

#pragma unroll
        for (int i = 0; i < 5; ++i) iv[i] = ivn[i];
        __syncwarp();
    }

    // ---- stats: butterfly over lanes sharing t4, then 4 atomics/lane ----
#pragma unroll
    for (int off = 4; off <= 16; off <<= 1) {
#pragma unroll
        for (int k = 0; k < 4; ++k) {
            s[k] += __shfl_xor_sync(0xffffffffu, s[k], off);
            qq[k] += __shfl_xor_sync(0xffffffffu, qq[k], off);
        }
    }
    if (lane < 4) {
        const int soff = FIRST ? 0 : 32;
        int ch[4] = {2 * lane, 2 * lane + 1, 2 * lane + 8, 2 * lane + 9};
#pragma unroll
        for (int k = 0; k < 4; ++k) {
            atomicAdd(&g_stats[soff + ch[k]], s[k]);
            atomicAdd(&g_stats[soff + 16 + ch[k]], qq[k]);
        }
    }
}

// ---------------------------------------------------------------------------
// k3: out = leaky(bn2(z2) + data)
// ---------------------------------------------------------------------------
__global__ __launch_bounds__(256) void k3_epilogue(
    const float* __restrict__ data, const float* __restrict__ gamma2,
    const float* __restrict__ beta2, float* __restrict__ out, int N, float invN)
{
    __shared__ float a2s[CC], c2s[CC];
    if (threadIdx.x < CC) {
        int o = threadIdx.x;
        float mean = g_stats[32 + o] * invN;
        float var = g_stats[48 + o] * invN - mean * mean;
        float a = gamma2[o] * rsqrtf(var + 1e-5f);
        a2s[o] = a;
        c2s[o] = fmaf(-mean, a, beta2[o]);
    }
    __syncthreads();
    int total4 = N * 4;
    const float4* z4 = reinterpret_cast<const float4*>(g_z2);
    const float4* d4 = reinterpret_cast<const float4*>(data);
    float4* o4 = reinterpret_cast<float4*>(out);
    for (int i = blockIdx.x * blockDim.x + threadIdx.x; i < total4;
         i += gridDim.x * blockDim.x) {
        float4 zv = z4[i];
        float4 dv = d4[i];
        int cb = (i & 3) * 4;
        float4 r;
        r.x = leaky(fmaf(a2s[cb + 0], zv.x, c2s[cb + 0]) + dv.x);
        r.y = leaky(fmaf(a2s[cb + 1], zv.y, c2s[cb + 1]) + dv.y);
        r.z = leaky(fmaf(a2s[cb + 2], zv.z, c2s[cb + 2]) + dv.z);
        r.w = leaky(fmaf(a2s[cb + 3], zv.w, c2s[cb + 3]) + dv.w);
        o4[i] = r;
    }
}

extern "C" void kernel_launch(void* const* d_in, const int* in_sizes, int n_in,
                              void* d_out, int out_size)
{
    const float* data   = (const float*)d_in[0];
    const int*   ind    = (const int*)d_in[1];
    const float* w1     = (const float*)d_in[2];
    const float* b1     = (const float*)d_in[3];
    const float* gamma1 = (const float*)d_in[4];
    const float* beta1  = (const float*)d_in[5];
    const float* w2     = (const float*)d_in[6];
    const float* gamma2 = (const float*)d_in[7];
    const float* beta2  = (const float*)d_in[8];

    int N = in_sizes[0] / CC;
    if (N > NMAX) N = NMAX;
    float invN = 1.0f / (float)N;
    int ntiles = (N + 15) / 16;

    k0_zero<<<1, 64>>>();
    conv_mma<true><<<GRID_CONV, TPB, SMEM_BYTES>>>(
        data, ind, w1, b1, nullptr, nullptr, N, ntiles, invN);
    conv_mma<false><<<GRID_CONV, TPB, SMEM_BYTES>>>(
        data, ind, w2, nullptr, gamma1, beta1, N, ntiles, invN);
    k3_epilogue<<<1024, 256>>>(data, gamma2, beta2, (float*)d_out, N, invN);
}